// round 14
// baseline (speedup 1.0000x reference)
#include <cuda_runtime.h>
#include <cuda_bf16.h>
#include <math.h>

// ---------------- problem constants ----------------
#define D_MODEL 512
#define D_FF    2048
#define NHEAD   8
#define DK      64
#define NLAYER  4
#define VOCAB   512
#define BATCH   16
#define LFULL   513
#define LT      512
#define SRC_S   256
#define MT      (BATCH*LT)
#define MS      (BATCH*SRC_S)

typedef __nv_bfloat16 bf16;
typedef __nv_bfloat162 bf162;

// ---------------- device scratch (static, no allocation) ----------------
__device__ float g_x  [MT*D_MODEL];                  // residual stream (fp32)
__device__ float g_pe [LT*D_MODEL];
__device__ float g_lg [MT*VOCAB];

__device__ bf16 g_hb [MT*D_MODEL];                   // ln output
__device__ bf16 g_qb [MT*D_MODEL];                   // cross-attn Q
__device__ bf16 g_qkv[MT*3*D_MODEL];                 // fused self QKV
__device__ bf16 g_kvL[NLAYER][MS*2*D_MODEL];         // per-layer cross KV (stream overlap)
__device__ bf16 g_ab [MT*D_MODEL];                   // attention output
__device__ bf16 g_fb [MT*D_FF];                      // ffn intermediate
__device__ bf16 g_wsa[NLAYER*4*D_MODEL*D_MODEL];     // only mat3 used
__device__ bf16 g_wca[NLAYER*4*D_MODEL*D_MODEL];     // only mats 0,3 used
__device__ bf16 g_wqkv[NLAYER*D_MODEL*3*D_MODEL];    // packed self QKV weights
__device__ bf16 g_wkv [NLAYER*D_MODEL*2*D_MODEL];    // packed cross KV weights
__device__ float g_bqkv[NLAYER*3*D_MODEL];
__device__ float g_bkv [NLAYER*2*D_MODEL];
__device__ bf16 g_w1 [NLAYER*D_MODEL*D_FF];
__device__ bf16 g_w2 [NLAYER*D_FF*D_MODEL];
__device__ bf16 g_wlm[D_MODEL*VOCAB];
__device__ bf16 g_srcb[MS*D_MODEL];

// ---------------- PTX helpers ----------------
__device__ __forceinline__ void cpa16(void* s, const void* g) {
    unsigned a = (unsigned)__cvta_generic_to_shared(s);
    asm volatile("cp.async.ca.shared.global [%0], [%1], 16;" :: "r"(a), "l"(g));
}
__device__ __forceinline__ void cp_commit() { asm volatile("cp.async.commit_group;"); }
__device__ __forceinline__ void cp_wait0()  { asm volatile("cp.async.wait_group 0;"); }
__device__ __forceinline__ void cp_wait1()  { asm volatile("cp.async.wait_group 1;"); }
__device__ __forceinline__ void ldm_x4(unsigned* r, const void* p) {
    unsigned a = (unsigned)__cvta_generic_to_shared(p);
    asm volatile("ldmatrix.sync.aligned.m8n8.x4.shared.b16 {%0,%1,%2,%3}, [%4];"
        : "=r"(r[0]), "=r"(r[1]), "=r"(r[2]), "=r"(r[3]) : "r"(a));
}
__device__ __forceinline__ void ldm_x4_t(unsigned* r, const void* p) {
    unsigned a = (unsigned)__cvta_generic_to_shared(p);
    asm volatile("ldmatrix.sync.aligned.m8n8.x4.trans.shared.b16 {%0,%1,%2,%3}, [%4];"
        : "=r"(r[0]), "=r"(r[1]), "=r"(r[2]), "=r"(r[3]) : "r"(a));
}
__device__ __forceinline__ void mmabf(float* c, const unsigned* a, const unsigned* b) {
    asm volatile(
        "mma.sync.aligned.m16n8k16.row.col.f32.bf16.bf16.f32 "
        "{%0,%1,%2,%3}, {%4,%5,%6,%7}, {%8,%9}, {%0,%1,%2,%3};"
        : "+f"(c[0]), "+f"(c[1]), "+f"(c[2]), "+f"(c[3])
        : "r"(a[0]), "r"(a[1]), "r"(a[2]), "r"(a[3]), "r"(b[0]), "r"(b[1]));
}
__device__ __forceinline__ unsigned packbf(float x, float y) {
    bf162 v = __float22bfloat162_rn(make_float2(x, y));
    return *(unsigned*)&v;
}

// ---------------- vectorized conversions / repacks ----------------
__global__ void f2bf4_kernel(const float4* __restrict__ s, uint2* __restrict__ d, int n4) {
    int i = blockIdx.x * blockDim.x + threadIdx.x;
    int stride = gridDim.x * blockDim.x;
    for (; i < n4; i += stride) {
        float4 v = s[i];
        uint2 o; o.x = packbf(v.x, v.y); o.y = packbf(v.z, v.w);
        d[i] = o;
    }
}
// convert the 3 used mats of [L][4][512][512] tensors in one kernel
__global__ void conv3_kernel(const float4* __restrict__ sa, const float4* __restrict__ ca,
                             uint2* __restrict__ wsa, uint2* __restrict__ wca) {
    const int per4 = NLAYER * D_MODEL * D_MODEL / 4;
    const int mm4  = D_MODEL * D_MODEL / 4;
    int i = blockIdx.x * blockDim.x + threadIdx.x;
    int stride = gridDim.x * blockDim.x;
    for (; i < 3 * per4; i += stride) {
        int seg = i / per4, r = i % per4;
        int l = r / mm4, q = r % mm4;
        int mat = (seg == 1) ? 0 : 3;
        const float4* src = (seg == 0) ? sa : ca;
        uint2* dst = (seg == 0) ? wsa : wca;
        size_t off = ((size_t)l * 4 + mat) * mm4 + q;
        float4 v = src[off];
        uint2 o; o.x = packbf(v.x, v.y); o.y = packbf(v.z, v.w);
        dst[off] = o;
    }
}
// [L][4][512][512] -> [L][512][nmat*512], vectorized by 4 along c
__global__ void pack_w4(const float* __restrict__ W, uint2* __restrict__ out,
                        int nmat, int mat0, int total4) {
    int i = blockIdx.x * blockDim.x + threadIdx.x;
    int stride = gridDim.x * blockDim.x;
    int perL4 = D_MODEL * nmat * D_MODEL / 4;
    for (; i < total4; i += stride) {
        int l = i / perL4, rem = i % perL4;
        int k = rem / (nmat * 128), j4 = rem % (nmat * 128);
        int j = j4 * 4;
        int m = mat0 + (j >> 9), c = j & 511;
        float4 v = *(const float4*)&W[(((size_t)l * 4 + m) * D_MODEL + k) * D_MODEL + c];
        uint2 o; o.x = packbf(v.x, v.y); o.y = packbf(v.z, v.w);
        out[i] = o;
    }
}
// both bias packs in one launch
__global__ void pack_b2(const float* __restrict__ Bsa, const float* __restrict__ Bca,
                        float* __restrict__ oq, float* __restrict__ okv) {
    const int nq = NLAYER * 3 * D_MODEL, nk = NLAYER * 2 * D_MODEL;
    int i = blockIdx.x * blockDim.x + threadIdx.x;
    if (i < nq) {
        int l = i / (3 * D_MODEL), j = i % (3 * D_MODEL);
        int m = j >> 9, c = j & 511;
        oq[i] = Bsa[((size_t)l * 4 + m) * D_MODEL + c];
    } else if (i < nq + nk) {
        int i2 = i - nq;
        int l = i2 / (2 * D_MODEL), j = i2 % (2 * D_MODEL);
        int m = 1 + (j >> 9), c = j & 511;
        okv[i2] = Bca[((size_t)l * 4 + m) * D_MODEL + c];
    }
}

// ---------------- positional encoding (fp64 to match numpy) ----------------
__global__ void pe_kernel() {
    int i = blockIdx.x * blockDim.x + threadIdx.x;
    if (i >= LT * D_MODEL) return;
    int t = i / D_MODEL, d = i % D_MODEL;
    int e = d & ~1;
    double div = exp(-(double)e * (log(10000.0) / (double)D_MODEL));
    double ang = (double)t * div;
    g_pe[i] = (float)((d & 1) ? cos(ang) : sin(ang));
}

// ---------------- embedding + PE ----------------
__global__ void embed_kernel(const int* __restrict__ ids, const float* __restrict__ emb) {
    int i = blockIdx.x * blockDim.x + threadIdx.x;
    if (i >= MT * D_MODEL) return;
    int row = i / D_MODEL, d = i % D_MODEL;
    int b = row / LT, t = row % LT;
    int tok = ids[b * LFULL + t];
    g_x[i] = emb[tok * D_MODEL + d] * 22.62741699796952f + g_pe[t * D_MODEL + d];
}

// ---------------- layernorm: warp per row (ddof=1, denom = std + eps) ----------------
__global__ void ln_kernel(const float* __restrict__ x, bf16* __restrict__ y,
                          const float* __restrict__ ga, const float* __restrict__ gb) {
    int w = threadIdx.x >> 5, lane = threadIdx.x & 31;
    int row = blockIdx.x * 8 + w;
    const float4* xr = (const float4*)(x + (size_t)row * D_MODEL);
    const float4* gav = (const float4*)ga;
    const float4* gbv = (const float4*)gb;
    bf16* yr = y + (size_t)row * D_MODEL;
    float4 v[4];
    float s = 0.f, s2 = 0.f;
#pragma unroll
    for (int j = 0; j < 4; j++) {
        v[j] = xr[lane + j * 32];
        s  += v[j].x + v[j].y + v[j].z + v[j].w;
        s2 += v[j].x * v[j].x + v[j].y * v[j].y + v[j].z * v[j].z + v[j].w * v[j].w;
    }
#pragma unroll
    for (int o = 16; o > 0; o >>= 1) {
        s  += __shfl_xor_sync(0xffffffffu, s,  o);
        s2 += __shfl_xor_sync(0xffffffffu, s2, o);
    }
    float mean = s / 512.0f;
    float var  = fmaxf(0.f, s2 - 512.0f * mean * mean) / 511.0f;
    float inv  = 1.0f / (sqrtf(var) + 1e-6f);
#pragma unroll
    for (int j = 0; j < 4; j++) {
        int c4 = lane + j * 32;
        float4 a = gav[c4], b = gbv[c4];
        float r0 = a.x * (v[j].x - mean) * inv + b.x;
        float r1 = a.y * (v[j].y - mean) * inv + b.y;
        float r2 = a.z * (v[j].z - mean) * inv + b.z;
        float r3 = a.w * (v[j].w - mean) * inv + b.w;
        *(bf162*)(yr + c4 * 4)     = __float22bfloat162_rn(make_float2(r0, r1));
        *(bf162*)(yr + c4 * 4 + 2) = __float22bfloat162_rn(make_float2(r2, r3));
    }
}

// =====================================================================
// bf16 tensor-core GEMM: C = A(MxK,row) @ W(KxN,row) + bias [+res][relu]
// BM=128 BN=128 BK=64, 3-stage cp.async ring, single sync/iter,
// 8 warps (2m x 4n), warp tile 64x32, 2 CTAs/SM (215KB smem/SM).
// =====================================================================
#define ASZ 18432   // 128 x 72 bf16
#define BSZ 17408   // 64 x 136 bf16
#define GEMM_SMEM (3*(ASZ+BSZ))

__global__ void __launch_bounds__(256, 2) gemm_bf(
        const bf16* __restrict__ A, const bf16* __restrict__ W,
        const float* __restrict__ bias, const float* __restrict__ res,
        bf16* __restrict__ Cb, float* __restrict__ Cf,
        int M, int N, int K, int relu) {
    extern __shared__ char smg[];
    int row0 = blockIdx.y * 128, col0 = blockIdx.x * 128;
    int tid = threadIdx.x;
    int wid = tid >> 5, lane = tid & 31;
    int g = lane >> 2, t = lane & 3;
    int wm = wid & 1, wn = wid >> 1;
    int tl = lane >> 3, rr = lane & 7;

    float c[4][4][4];
#pragma unroll
    for (int i = 0; i < 4; i++)
#pragma unroll
        for (int j = 0; j < 4; j++)
#pragma unroll
            for (int r = 0; r < 4; r++) c[i][j][r] = 0.f;

    int nIter = K >> 6;   // BK = 64
    auto loadStage = [&](int st, int k0g) {
        bf16 (*As)[72]  = (bf16(*)[72])(smg + st * ASZ);
        bf16 (*Bs)[136] = (bf16(*)[136])(smg + 3 * ASZ + st * BSZ);
#pragma unroll
        for (int i = 0; i < 4; i++) {
            int idx = tid + i * 256;
            int m = idx >> 3, kq = (idx & 7) * 8;
            cpa16(&As[m][kq], A + (size_t)(row0 + m) * K + k0g + kq);
        }
#pragma unroll
        for (int i = 0; i < 4; i++) {
            int idx = tid + i * 256;
            int k = idx >> 4, nq = (idx & 15) * 8;
            cpa16(&Bs[k][nq], W + (size_t)(k0g + k) * N + col0 + nq);
        }
    };
#pragma unroll
    for (int p = 0; p < 2; p++) {
        if (p < nIter) loadStage(p, p << 6);
        cp_commit();
    }
    for (int it = 0; it < nIter; ++it) {
        int st = it % 3;
        bf16 (*As)[72]  = (bf16(*)[72])(smg + st * ASZ);
        bf16 (*Bs)[136] = (bf16(*)[136])(smg + 3 * ASZ + st * BSZ);
        if (it + 1 < nIter) cp_wait1(); else cp_wait0();
        __syncthreads();
        int nx = it + 2;
        if (nx < nIter) loadStage(nx % 3, nx << 6);
        cp_commit();
#pragma unroll
        for (int ks = 0; ks < 4; ks++) {
            int k0 = ks * 16;
            unsigned af[4][4];
#pragma unroll
            for (int mt = 0; mt < 4; mt++)
                ldm_x4(af[mt], &As[wm * 64 + mt * 16 + (lane & 15)][k0 + (lane >> 4) * 8]);
            unsigned bf[4][2];
#pragma unroll
            for (int nb = 0; nb < 2; nb++) {
                unsigned r4[4];
                ldm_x4_t(r4, &Bs[k0 + (tl & 1) * 8 + rr][wn * 32 + nb * 16 + (tl >> 1) * 8]);
                bf[nb * 2 + 0][0] = r4[0]; bf[nb * 2 + 0][1] = r4[1];
                bf[nb * 2 + 1][0] = r4[2]; bf[nb * 2 + 1][1] = r4[3];
            }
#pragma unroll
            for (int mt = 0; mt < 4; mt++)
#pragma unroll
                for (int nt = 0; nt < 4; nt++) mmabf(c[mt][nt], af[mt], bf[nt]);
        }
    }
#pragma unroll
    for (int mt = 0; mt < 4; mt++) {
        int r = row0 + wm * 64 + mt * 16 + g;
#pragma unroll
        for (int nt = 0; nt < 4; nt++) {
            int cc = col0 + wn * 32 + nt * 8 + 2 * t;
            float b0 = bias[cc], b1 = bias[cc + 1];
            float v0 = c[mt][nt][0] + b0, v1 = c[mt][nt][1] + b1;
            float v2 = c[mt][nt][2] + b0, v3 = c[mt][nt][3] + b1;
            if (res) {
                v0 += res[(size_t)r * N + cc];       v1 += res[(size_t)r * N + cc + 1];
                v2 += res[(size_t)(r + 8) * N + cc]; v3 += res[(size_t)(r + 8) * N + cc + 1];
            }
            if (relu) {
                v0 = fmaxf(v0, 0.f); v1 = fmaxf(v1, 0.f);
                v2 = fmaxf(v2, 0.f); v3 = fmaxf(v3, 0.f);
            }
            if (Cf) {
                *(float2*)(Cf + (size_t)r * N + cc)       = make_float2(v0, v1);
                *(float2*)(Cf + (size_t)(r + 8) * N + cc) = make_float2(v2, v3);
            }
            if (Cb) {
                *(bf162*)(Cb + (size_t)r * N + cc)       = __float22bfloat162_rn(make_float2(v0, v1));
                *(bf162*)(Cb + (size_t)(r + 8) * N + cc) = __float22bfloat162_rn(make_float2(v2, v3));
            }
        }
    }
}

// =====================================================================
// Fused flash attention (unchanged; LPT for causal)
// =====================================================================
#define KVB 36864
#define FLASH_SMEM (18432 + 2*KVB + 1024)

template <int CAUSAL>
__global__ void __launch_bounds__(256, 1) flash_kernel(
        const bf16* __restrict__ Qp, int qStride,
        const bf16* __restrict__ Kp, const bf16* __restrict__ Vp, int kvStride,
        const int* __restrict__ mask, int maskStride,
        bf16* __restrict__ Op, int Lq, int Lk) {
    extern __shared__ char sm[];
    bf16 (*Qs)[72] = (bf16(*)[72])(sm);
    int* mS = (int*)(sm + 18432 + 2 * KVB);

    int bx = CAUSAL ? (gridDim.x - 1 - blockIdx.x) : blockIdx.x;
    int m0 = bx * 128;
    int z = blockIdx.y, b = z / NHEAD, h = z % NHEAD;
    const bf16* Qb = Qp + (size_t)b * Lq * qStride + h * DK;
    const bf16* Kb = Kp + (size_t)b * Lk * kvStride + h * DK;
    const bf16* Vb = Vp + (size_t)b * Lk * kvStride + h * DK;
    bf16* Ob = Op + (size_t)b * Lq * D_MODEL + h * DK;
    const int* mrow = mask + (size_t)b * maskStride;

    int tid = threadIdx.x, w = tid >> 5, lane = tid & 31;
    int g = lane >> 2, t = lane & 3;
    int tl = lane >> 3, rr = lane & 7;
    const float scale = 0.125f;

    auto loadKV = [&](int buf, int n0) {
        bf16 (*Ks)[72] = (bf16(*)[72])(sm + 18432 + buf * KVB);
        bf16 (*Vs)[72] = (bf16(*)[72])(sm + 18432 + buf * KVB + KVB / 2);
#pragma unroll
        for (int i = 0; i < 4; i++) {
            int idx = tid + i * 256;
            int r = idx >> 3, cq = (idx & 7) * 8;
            cpa16(&Ks[r][cq], Kb + (size_t)(n0 + r) * kvStride + cq);
            cpa16(&Vs[r][cq], Vb + (size_t)(n0 + r) * kvStride + cq);
        }
        if (tid < 128) mS[buf * 128 + tid] = mrow[n0 + tid];
    };

    int nChunks = CAUSAL ? (m0 / 128 + 1) : (Lk / 128);

#pragma unroll
    for (int i = 0; i < 4; i++) {
        int idx = tid + i * 256;
        int r = idx >> 3, cq = (idx & 7) * 8;
        cpa16(&Qs[r][cq], Qb + (size_t)(m0 + r) * qStride + cq);
    }
    cp_commit();
    loadKV(0, 0);
    cp_commit();
    cp_wait1();
    __syncthreads();

    unsigned qf[4][4];
#pragma unroll
    for (int ks = 0; ks < 4; ks++)
        ldm_x4(qf[ks], &Qs[w * 16 + (lane & 15)][ks * 16 + (lane >> 4) * 8]);

    float o[8][4];
#pragma unroll
    for (int i = 0; i < 8; i++)
#pragma unroll
        for (int j = 0; j < 4; j++) o[i][j] = 0.f;
    float mrun[2] = {-1e30f, -1e30f}, lrun[2] = {0.f, 0.f};
    int rowg = m0 + w * 16 + g;

    for (int ch = 0; ch < nChunks; ch++) {
        int n0 = ch * 128;
        int bu = ch & 1;
        bf16 (*Ks)[72] = (bf16(*)[72])(sm + 18432 + bu * KVB);
        bf16 (*Vs)[72] = (bf16(*)[72])(sm + 18432 + bu * KVB + KVB / 2);
        const int* mSb = mS + bu * 128;
        if (ch + 1 < nChunks) { loadKV(bu ^ 1, n0 + 128); cp_commit(); cp_wait1(); }
        else                  { cp_commit(); cp_wait0(); }
        __syncthreads();

        float s[16][4];
#pragma unroll
        for (int nt = 0; nt < 16; nt++)
#pragma unroll
            for (int j = 0; j < 4; j++) s[nt][j] = 0.f;
#pragma unroll
        for (int ks = 0; ks < 4; ks++) {
            int k0 = ks * 16;
#pragma unroll
            for (int nt = 0; nt < 16; nt++) {
                unsigned bfr[2];
                int nc = nt * 8 + g;
                bfr[0] = *(const unsigned*)&Ks[nc][k0 + 2 * t];
                bfr[1] = *(const unsigned*)&Ks[nc][k0 + 8 + 2 * t];
                mmabf(s[nt], qf[ks], bfr);
            }
        }
#pragma unroll
        for (int nt = 0; nt < 16; nt++) {
            int cl = nt * 8 + 2 * t;
            int c0 = n0 + cl, c1 = c0 + 1;
            bool k0ok = mSb[cl] != 0, k1ok = mSb[cl + 1] != 0;
            bool v0 = k0ok && (!CAUSAL || c0 <= rowg);
            bool v1 = k1ok && (!CAUSAL || c1 <= rowg);
            bool v2 = k0ok && (!CAUSAL || c0 <= rowg + 8);
            bool v3 = k1ok && (!CAUSAL || c1 <= rowg + 8);
            s[nt][0] = v0 ? s[nt][0] * scale : -10000.0f;
            s[nt][1] = v1 ? s[nt][1] * scale : -10000.0f;
            s[nt][2] = v2 ? s[nt][2] * scale : -10000.0f;
            s[nt][3] = v3 ? s[nt][3] * scale : -10000.0f;
        }
        float mg0 = -1e30f, mg1 = -1e30f;
#pragma unroll
        for (int nt = 0; nt < 16; nt++) {
            mg0 = fmaxf(mg0, fmaxf(s[nt][0], s[nt][1]));
            mg1 = fmaxf(mg1, fmaxf(s[nt][2], s[nt][3]));
        }
#pragma unroll
        for (int off = 1; off < 4; off <<= 1) {
            mg0 = fmaxf(mg0, __shfl_xor_sync(0xffffffffu, mg0, off));
            mg1 = fmaxf(mg1, __shfl_xor_sync(0xffffffffu, mg1, off));
        }
        float mn0 = fmaxf(mrun[0], mg0), mn1 = fmaxf(mrun[1], mg1);
        float a0 = __expf(mrun[0] - mn0), a1 = __expf(mrun[1] - mn1);
        float sum0 = 0.f, sum1 = 0.f;
#pragma unroll
        for (int nt = 0; nt < 16; nt++) {
            s[nt][0] = __expf(s[nt][0] - mn0);
            s[nt][1] = __expf(s[nt][1] - mn0);
            s[nt][2] = __expf(s[nt][2] - mn1);
            s[nt][3] = __expf(s[nt][3] - mn1);
            sum0 += s[nt][0] + s[nt][1];
            sum1 += s[nt][2] + s[nt][3];
        }
#pragma unroll
        for (int off = 1; off < 4; off <<= 1) {
            sum0 += __shfl_xor_sync(0xffffffffu, sum0, off);
            sum1 += __shfl_xor_sync(0xffffffffu, sum1, off);
        }
        lrun[0] = lrun[0] * a0 + sum0;
        lrun[1] = lrun[1] * a1 + sum1;
        mrun[0] = mn0; mrun[1] = mn1;
#pragma unroll
        for (int ot = 0; ot < 8; ot++) {
            o[ot][0] *= a0; o[ot][1] *= a0;
            o[ot][2] *= a1; o[ot][3] *= a1;
        }
#pragma unroll
        for (int j = 0; j < 8; j++) {
            unsigned pa[4];
            pa[0] = packbf(s[2 * j][0],     s[2 * j][1]);
            pa[1] = packbf(s[2 * j][2],     s[2 * j][3]);
            pa[2] = packbf(s[2 * j + 1][0], s[2 * j + 1][1]);
            pa[3] = packbf(s[2 * j + 1][2], s[2 * j + 1][3]);
#pragma unroll
            for (int nb = 0; nb < 4; nb++) {
                unsigned r4[4];
                ldm_x4_t(r4, &Vs[j * 16 + (tl & 1) * 8 + rr][nb * 16 + (tl >> 1) * 8]);
                mmabf(o[nb * 2 + 0], pa, r4);
                mmabf(o[nb * 2 + 1], pa, r4 + 2);
            }
        }
        __syncthreads();
    }
    float inv0 = 1.0f / lrun[0], inv1 = 1.0f / lrun[1];
#pragma unroll
    for (int ot = 0; ot < 8; ot++) {
        int col = ot * 8 + 2 * t;
        *(bf162*)(Ob + (size_t)rowg * D_MODEL + col) =
            __float22bfloat162_rn(make_float2(o[ot][0] * inv0, o[ot][1] * inv0));
        *(bf162*)(Ob + (size_t)(rowg + 8) * D_MODEL + col) =
            __float22bfloat162_rn(make_float2(o[ot][2] * inv1, o[ot][3] * inv1));
    }
}

// ---------------- final log_softmax (warp per row, 512 cols) ----------------
__global__ void logsoftmax_kernel(const float* __restrict__ X, float* __restrict__ Out) {
    int warp = (blockIdx.x * blockDim.x + threadIdx.x) >> 5;
    int lane = threadIdx.x & 31;
    if (warp >= MT) return;
    const float* r = X + (size_t)warp * VOCAB;
    float v[16], mx = -1e30f;
#pragma unroll
    for (int j = 0; j < 16; j++) { v[j] = r[lane + j * 32]; mx = fmaxf(mx, v[j]); }
#pragma unroll
    for (int o = 16; o > 0; o >>= 1) mx = fmaxf(mx, __shfl_xor_sync(0xffffffffu, mx, o));
    float sum = 0.f;
#pragma unroll
    for (int j = 0; j < 16; j++) sum += expf(v[j] - mx);
#pragma unroll
    for (int o = 16; o > 0; o >>= 1) sum += __shfl_xor_sync(0xffffffffu, sum, o);
    float lse = mx + logf(sum);
    float* out = Out + (size_t)warp * VOCAB;
#pragma unroll
    for (int j = 0; j < 16; j++) out[lane + j * 32] = v[j] - lse;
}

// ---------------- host driver ----------------
template <typename T>
static T* symp(const void* s) {
    void* p = nullptr;
    cudaGetSymbolAddress(&p, s);
    return (T*)p;
}

extern "C" void kernel_launch(void* const* d_in, const int* in_sizes, int n_in,
                              void* d_out, int out_size) {
    const int*   ids    = (const int*)d_in[0];
    const int*   attm   = (const int*)d_in[1];
    const float* src    = (const float*)d_in[2];
    const int*   srcm   = (const int*)d_in[3];
    const float* emb    = (const float*)d_in[4];
    const float* sa_W   = (const float*)d_in[5];
    const float* sa_b   = (const float*)d_in[6];
    const float* ca_W   = (const float*)d_in[7];
    const float* ca_b   = (const float*)d_in[8];
    const float* ln_a   = (const float*)d_in[9];
    const float* ln_b   = (const float*)d_in[10];
    const float* ffn_w1 = (const float*)d_in[11];
    const float* ffn_b1 = (const float*)d_in[12];
    const float* ffn_w2 = (const float*)d_in[13];
    const float* ffn_b2 = (const float*)d_in[14];
    const float* fin_a  = (const float*)d_in[15];
    const float* fin_b  = (const float*)d_in[16];
    const float* lm_W   = (const float*)d_in[17];
    const float* lm_b   = (const float*)d_in[18];
    float* out = (float*)d_out;

    float* x    = symp<float>(g_x);
    float* lg   = symp<float>(g_lg);
    bf16* hb    = symp<bf16>(g_hb);
    bf16* qb    = symp<bf16>(g_qb);
    bf16* qkv   = symp<bf16>(g_qkv);
    bf16* kvL   = symp<bf16>(g_kvL);
    bf16* ab    = symp<bf16>(g_ab);
    bf16* fb    = symp<bf16>(g_fb);
    bf16* wsa   = symp<bf16>(g_wsa);
    bf16* wca   = symp<bf16>(g_wca);
    bf16* wqkv  = symp<bf16>(g_wqkv);
    bf16* wkv   = symp<bf16>(g_wkv);
    float* bqkv = symp<float>(g_bqkv);
    float* bkv  = symp<float>(g_bkv);
    bf16* w1    = symp<bf16>(g_w1);
    bf16* w2    = symp<bf16>(g_w2);
    bf16* wlm   = symp<bf16>(g_wlm);
    bf16* srcb  = symp<bf16>(g_srcb);

    static bool inited = false;
    static cudaStream_t s2;
    static cudaEvent_t evFork, evKv[NLAYER];
    if (!inited) {
        cudaFuncSetAttribute(flash_kernel<1>, cudaFuncAttributeMaxDynamicSharedMemorySize, FLASH_SMEM);
        cudaFuncSetAttribute(flash_kernel<0>, cudaFuncAttributeMaxDynamicSharedMemorySize, FLASH_SMEM);
        cudaFuncSetAttribute(gemm_bf, cudaFuncAttributeMaxDynamicSharedMemorySize, GEMM_SMEM);
        cudaStreamCreateWithFlags(&s2, cudaStreamNonBlocking);
        cudaEventCreateWithFlags(&evFork, cudaEventDisableTiming);
        for (int i = 0; i < NLAYER; i++)
            cudaEventCreateWithFlags(&evKv[i], cudaEventDisableTiming);
        inited = true;
    }

    // ---- one-time-per-launch conversions / repacks ----
    {
        int nF4 = NLAYER * D_MODEL * D_FF / 4;
        conv3_kernel<<<2048, 256>>>((const float4*)sa_W, (const float4*)ca_W,
                                    (uint2*)wsa, (uint2*)wca);
        f2bf4_kernel<<<(nF4 + 1023) / 1024, 256>>>((const float4*)ffn_w1, (uint2*)w1, nF4);
        f2bf4_kernel<<<(nF4 + 1023) / 1024, 256>>>((const float4*)ffn_w2, (uint2*)w2, nF4);
        f2bf4_kernel<<<(D_MODEL * VOCAB / 4 + 1023) / 1024, 256>>>((const float4*)lm_W, (uint2*)wlm, D_MODEL * VOCAB / 4);
        f2bf4_kernel<<<(MS * D_MODEL / 4 + 1023) / 1024, 256>>>((const float4*)src, (uint2*)srcb, MS * D_MODEL / 4);
        int tq4 = NLAYER * D_MODEL * 3 * D_MODEL / 4;
        int tk4 = NLAYER * D_MODEL * 2 * D_MODEL / 4;
        pack_w4<<<(tq4 + 1023) / 1024, 256>>>(sa_W, (uint2*)wqkv, 3, 0, tq4);
        pack_w4<<<(tk4 + 1023) / 1024, 256>>>(ca_W, (uint2*)wkv, 2, 1, tk4);
        pack_b2<<<(NLAYER * 5 * D_MODEL + 255) / 256, 256>>>(sa_b, ca_b, bqkv, bkv);
    }

    // ---- fork: all 4 cross-KV projections on s2 (depend only on prep) ----
    dim3 gKV(2 * D_MODEL / 128, MS / 128);    // (8, 32)
    cudaEventRecord(evFork, 0);
    cudaStreamWaitEvent(s2, evFork, 0);
    for (int i = 0; i < NLAYER; i++) {
        gemm_bf<<<gKV, 256, GEMM_SMEM, s2>>>(srcb, wkv + (size_t)i * D_MODEL * 2 * D_MODEL,
                              bkv + (size_t)i * 2 * D_MODEL, nullptr,
                              kvL + (size_t)i * MS * 2 * D_MODEL, nullptr,
                              MS, 2 * D_MODEL, D_MODEL, 0);
        cudaEventRecord(evKv[i], s2);
    }

    pe_kernel<<<(LT * D_MODEL + 255) / 256, 256>>>();
    embed_kernel<<<(MT * D_MODEL + 255) / 256, 256>>>(ids, emb);

    dim3 gProjT(D_MODEL / 128, MT / 128);     // (4, 64)
    dim3 gQKV(3 * D_MODEL / 128, MT / 128);   // (12, 64)
    dim3 gFfn1(D_FF / 128, MT / 128);         // (16, 64)
    dim3 gFlash(LT / 128, BATCH * NHEAD);
    const int lnGrid = MT / 8;

    for (int i = 0; i < NLAYER; i++) {
        const bf16*  saW = wsa + (size_t)i * 4 * D_MODEL * D_MODEL;
        const float* sab = sa_b + (size_t)i * 4 * D_MODEL;
        const bf16*  caW = wca + (size_t)i * 4 * D_MODEL * D_MODEL;
        const float* cab = ca_b + (size_t)i * 4 * D_MODEL;
        const float* lnA = ln_a + (size_t)i * 3 * D_MODEL;
        const float* lnB = ln_b + (size_t)i * 3 * D_MODEL;
        bf16* kvi = kvL + (size_t)i * MS * 2 * D_MODEL;

        // ---- self-attention ----
        ln_kernel<<<lnGrid, 256>>>(x, hb, lnA + 0 * D_MODEL, lnB + 0 * D_MODEL);
        gemm_bf<<<gQKV, 256, GEMM_SMEM>>>(hb, wqkv + (size_t)i * D_MODEL * 3 * D_MODEL,
                               bqkv + (size_t)i * 3 * D_MODEL, nullptr, qkv, nullptr,
                               MT, 3 * D_MODEL, D_MODEL, 0);
        flash_kernel<1><<<gFlash, 256, FLASH_SMEM>>>(
            qkv, 3 * D_MODEL, qkv + D_MODEL, qkv + 2 * D_MODEL, 3 * D_MODEL,
            attm, LFULL, ab, LT, LT);
        gemm_bf<<<gProjT, 256, GEMM_SMEM>>>(ab, saW + 3 * D_MODEL * D_MODEL, sab + 3 * D_MODEL,
                                 x, nullptr, x, MT, D_MODEL, D_MODEL, 0);

        // ---- cross-attention ----
        ln_kernel<<<lnGrid, 256>>>(x, hb, lnA + 1 * D_MODEL, lnB + 1 * D_MODEL);
        gemm_bf<<<gProjT, 256, GEMM_SMEM>>>(hb, caW + 0 * D_MODEL * D_MODEL, cab + 0 * D_MODEL,
                                 nullptr, qb, nullptr, MT, D_MODEL, D_MODEL, 0);
        cudaStreamWaitEvent(0, evKv[i], 0);
        flash_kernel<0><<<gFlash, 256, FLASH_SMEM>>>(
            qb, D_MODEL, kvi, kvi + D_MODEL, 2 * D_MODEL,
            srcm, SRC_S, ab, LT, SRC_S);
        gemm_bf<<<gProjT, 256, GEMM_SMEM>>>(ab, caW + 3 * D_MODEL * D_MODEL, cab + 3 * D_MODEL,
                                 x, nullptr, x, MT, D_MODEL, D_MODEL, 0);

        // ---- FFN ----
        ln_kernel<<<lnGrid, 256>>>(x, hb, lnA + 2 * D_MODEL, lnB + 2 * D_MODEL);
        gemm_bf<<<gFfn1, 256, GEMM_SMEM>>>(hb, w1 + (size_t)i * D_MODEL * D_FF,
                                ffn_b1 + (size_t)i * D_FF, nullptr, fb, nullptr,
                                MT, D_FF, D_MODEL, 1);
        gemm_bf<<<gProjT, 256, GEMM_SMEM>>>(fb, w2 + (size_t)i * D_FF * D_MODEL,
                                ffn_b2 + (size_t)i * D_MODEL, x, nullptr, x,
                                MT, D_MODEL, D_FF, 0);
    }

    ln_kernel<<<lnGrid, 256>>>(x, hb, fin_a, fin_b);
    gemm_bf<<<dim3(VOCAB / 128, MT / 128), 256, GEMM_SMEM>>>(hb, wlm, lm_b, nullptr, nullptr, lg,
                                                  MT, VOCAB, D_MODEL, 0);
    logsoftmax_kernel<<<(MT * 32 + 255) / 256, 256>>>(lg, out);
}

// round 16
// speedup vs baseline: 1.0867x; 1.0867x over previous
#include <cuda_runtime.h>
#include <cuda_bf16.h>
#include <math.h>

// ---------------- problem constants ----------------
#define D_MODEL 512
#define D_FF    2048
#define NHEAD   8
#define DK      64
#define NLAYER  4
#define VOCAB   512
#define BATCH   16
#define LFULL   513
#define LT      512
#define SRC_S   256
#define MT      (BATCH*LT)
#define MS      (BATCH*SRC_S)

typedef __nv_bfloat16 bf16;
typedef __nv_bfloat162 bf162;

// ---------------- device scratch (static, no allocation) ----------------
__device__ float g_x  [MT*D_MODEL];                  // residual stream (fp32)
__device__ float g_pe [LT*D_MODEL];
__device__ float g_lg [MT*VOCAB];

__device__ bf16 g_hb [MT*D_MODEL];                   // ln output
__device__ bf16 g_qb [MT*D_MODEL];                   // cross-attn Q
__device__ bf16 g_qkv[MT*3*D_MODEL];                 // fused self QKV
__device__ bf16 g_kvL[NLAYER][MS*2*D_MODEL];         // per-layer cross KV (stream overlap)
__device__ bf16 g_ab [MT*D_MODEL];                   // attention output
__device__ bf16 g_fb [MT*D_FF];                      // ffn intermediate
__device__ bf16 g_wsa[NLAYER*4*D_MODEL*D_MODEL];     // only mat3 used
__device__ bf16 g_wca[NLAYER*4*D_MODEL*D_MODEL];     // only mats 0,3 used
__device__ bf16 g_wqkv[NLAYER*D_MODEL*3*D_MODEL];    // packed self QKV weights
__device__ bf16 g_wkv [NLAYER*D_MODEL*2*D_MODEL];    // packed cross KV weights
__device__ float g_bqkv[NLAYER*3*D_MODEL];
__device__ float g_bkv [NLAYER*2*D_MODEL];
__device__ bf16 g_w1 [NLAYER*D_MODEL*D_FF];
__device__ bf16 g_w2 [NLAYER*D_FF*D_MODEL];
__device__ bf16 g_wlm[D_MODEL*VOCAB];
__device__ bf16 g_srcb[MS*D_MODEL];

// ---------------- PTX helpers ----------------
__device__ __forceinline__ void cpa16(void* s, const void* g) {
    unsigned a = (unsigned)__cvta_generic_to_shared(s);
    asm volatile("cp.async.cg.shared.global [%0], [%1], 16;" :: "r"(a), "l"(g));
}
__device__ __forceinline__ void cp_commit() { asm volatile("cp.async.commit_group;"); }
__device__ __forceinline__ void cp_wait0()  { asm volatile("cp.async.wait_group 0;"); }
__device__ __forceinline__ void cp_wait1()  { asm volatile("cp.async.wait_group 1;"); }
__device__ __forceinline__ void ldm_x4(unsigned* r, const void* p) {
    unsigned a = (unsigned)__cvta_generic_to_shared(p);
    asm volatile("ldmatrix.sync.aligned.m8n8.x4.shared.b16 {%0,%1,%2,%3}, [%4];"
        : "=r"(r[0]), "=r"(r[1]), "=r"(r[2]), "=r"(r[3]) : "r"(a));
}
__device__ __forceinline__ void ldm_x4_t(unsigned* r, const void* p) {
    unsigned a = (unsigned)__cvta_generic_to_shared(p);
    asm volatile("ldmatrix.sync.aligned.m8n8.x4.trans.shared.b16 {%0,%1,%2,%3}, [%4];"
        : "=r"(r[0]), "=r"(r[1]), "=r"(r[2]), "=r"(r[3]) : "r"(a));
}
__device__ __forceinline__ void mmabf(float* c, const unsigned* a, const unsigned* b) {
    asm volatile(
        "mma.sync.aligned.m16n8k16.row.col.f32.bf16.bf16.f32 "
        "{%0,%1,%2,%3}, {%4,%5,%6,%7}, {%8,%9}, {%0,%1,%2,%3};"
        : "+f"(c[0]), "+f"(c[1]), "+f"(c[2]), "+f"(c[3])
        : "r"(a[0]), "r"(a[1]), "r"(a[2]), "r"(a[3]), "r"(b[0]), "r"(b[1]));
}
__device__ __forceinline__ unsigned packbf(float x, float y) {
    bf162 v = __float22bfloat162_rn(make_float2(x, y));
    return *(unsigned*)&v;
}

// ---------------- vectorized conversions / repacks ----------------
__global__ void f2bf4_kernel(const float4* __restrict__ s, uint2* __restrict__ d, int n4) {
    int i = blockIdx.x * blockDim.x + threadIdx.x;
    int stride = gridDim.x * blockDim.x;
    for (; i < n4; i += stride) {
        float4 v = s[i];
        uint2 o; o.x = packbf(v.x, v.y); o.y = packbf(v.z, v.w);
        d[i] = o;
    }
}
// convert the 3 used mats of [L][4][512][512] tensors in one kernel
__global__ void conv3_kernel(const float4* __restrict__ sa, const float4* __restrict__ ca,
                             uint2* __restrict__ wsa, uint2* __restrict__ wca) {
    const int per4 = NLAYER * D_MODEL * D_MODEL / 4;
    const int mm4  = D_MODEL * D_MODEL / 4;
    int i = blockIdx.x * blockDim.x + threadIdx.x;
    int stride = gridDim.x * blockDim.x;
    for (; i < 3 * per4; i += stride) {
        int seg = i / per4, r = i % per4;
        int l = r / mm4, q = r % mm4;
        int mat = (seg == 1) ? 0 : 3;
        const float4* src = (seg == 0) ? sa : ca;
        uint2* dst = (seg == 0) ? wsa : wca;
        size_t off = ((size_t)l * 4 + mat) * mm4 + q;
        float4 v = src[off];
        uint2 o; o.x = packbf(v.x, v.y); o.y = packbf(v.z, v.w);
        dst[off] = o;
    }
}
// [L][4][512][512] -> [L][512][nmat*512], vectorized by 4 along c
__global__ void pack_w4(const float* __restrict__ W, uint2* __restrict__ out,
                        int nmat, int mat0, int total4) {
    int i = blockIdx.x * blockDim.x + threadIdx.x;
    int stride = gridDim.x * blockDim.x;
    int perL4 = D_MODEL * nmat * D_MODEL / 4;
    for (; i < total4; i += stride) {
        int l = i / perL4, rem = i % perL4;
        int k = rem / (nmat * 128), j4 = rem % (nmat * 128);
        int j = j4 * 4;
        int m = mat0 + (j >> 9), c = j & 511;
        float4 v = *(const float4*)&W[(((size_t)l * 4 + m) * D_MODEL + k) * D_MODEL + c];
        uint2 o; o.x = packbf(v.x, v.y); o.y = packbf(v.z, v.w);
        out[i] = o;
    }
}
// both bias packs in one launch
__global__ void pack_b2(const float* __restrict__ Bsa, const float* __restrict__ Bca,
                        float* __restrict__ oq, float* __restrict__ okv) {
    const int nq = NLAYER * 3 * D_MODEL, nk = NLAYER * 2 * D_MODEL;
    int i = blockIdx.x * blockDim.x + threadIdx.x;
    if (i < nq) {
        int l = i / (3 * D_MODEL), j = i % (3 * D_MODEL);
        int m = j >> 9, c = j & 511;
        oq[i] = Bsa[((size_t)l * 4 + m) * D_MODEL + c];
    } else if (i < nq + nk) {
        int i2 = i - nq;
        int l = i2 / (2 * D_MODEL), j = i2 % (2 * D_MODEL);
        int m = 1 + (j >> 9), c = j & 511;
        okv[i2] = Bca[((size_t)l * 4 + m) * D_MODEL + c];
    }
}

// ---------------- positional encoding (fp64 to match numpy) ----------------
__global__ void pe_kernel() {
    int i = blockIdx.x * blockDim.x + threadIdx.x;
    if (i >= LT * D_MODEL) return;
    int t = i / D_MODEL, d = i % D_MODEL;
    int e = d & ~1;
    double div = exp(-(double)e * (log(10000.0) / (double)D_MODEL));
    double ang = (double)t * div;
    g_pe[i] = (float)((d & 1) ? cos(ang) : sin(ang));
}

// ---------------- embedding + PE ----------------
__global__ void embed_kernel(const int* __restrict__ ids, const float* __restrict__ emb) {
    int i = blockIdx.x * blockDim.x + threadIdx.x;
    if (i >= MT * D_MODEL) return;
    int row = i / D_MODEL, d = i % D_MODEL;
    int b = row / LT, t = row % LT;
    int tok = ids[b * LFULL + t];
    g_x[i] = emb[tok * D_MODEL + d] * 22.62741699796952f + g_pe[t * D_MODEL + d];
}

// ---------------- layernorm: warp per row (ddof=1, denom = std + eps) ----------------
__global__ void ln_kernel(const float* __restrict__ x, bf16* __restrict__ y,
                          const float* __restrict__ ga, const float* __restrict__ gb) {
    int w = threadIdx.x >> 5, lane = threadIdx.x & 31;
    int row = blockIdx.x * 8 + w;
    const float4* xr = (const float4*)(x + (size_t)row * D_MODEL);
    const float4* gav = (const float4*)ga;
    const float4* gbv = (const float4*)gb;
    bf16* yr = y + (size_t)row * D_MODEL;
    float4 v[4];
    float s = 0.f, s2 = 0.f;
#pragma unroll
    for (int j = 0; j < 4; j++) {
        v[j] = xr[lane + j * 32];
        s  += v[j].x + v[j].y + v[j].z + v[j].w;
        s2 += v[j].x * v[j].x + v[j].y * v[j].y + v[j].z * v[j].z + v[j].w * v[j].w;
    }
#pragma unroll
    for (int o = 16; o > 0; o >>= 1) {
        s  += __shfl_xor_sync(0xffffffffu, s,  o);
        s2 += __shfl_xor_sync(0xffffffffu, s2, o);
    }
    float mean = s / 512.0f;
    float var  = fmaxf(0.f, s2 - 512.0f * mean * mean) / 511.0f;
    float inv  = 1.0f / (sqrtf(var) + 1e-6f);
#pragma unroll
    for (int j = 0; j < 4; j++) {
        int c4 = lane + j * 32;
        float4 a = gav[c4], b = gbv[c4];
        float r0 = a.x * (v[j].x - mean) * inv + b.x;
        float r1 = a.y * (v[j].y - mean) * inv + b.y;
        float r2 = a.z * (v[j].z - mean) * inv + b.z;
        float r3 = a.w * (v[j].w - mean) * inv + b.w;
        *(bf162*)(yr + c4 * 4)     = __float22bfloat162_rn(make_float2(r0, r1));
        *(bf162*)(yr + c4 * 4 + 2) = __float22bfloat162_rn(make_float2(r2, r3));
    }
}

// =====================================================================
// bf16 tensor-core GEMM: C = A(MxK,row) @ W(KxN,row) + bias [+res][relu]
// BM=128 BN=128 BK=32, 3-stage cp.async ring, single sync/iter,
// 8 warps (2m x 4n), warp tile 64x32, 2 CTAs/SM.  (R12 champion config)
// =====================================================================
#define ASZ 10240   // 128 x 40 bf16
#define BSZ 8704    // 32 x 136 bf16
#define GEMM_SMEM (3*(ASZ+BSZ))

__global__ void __launch_bounds__(256, 2) gemm_bf(
        const bf16* __restrict__ A, const bf16* __restrict__ W,
        const float* __restrict__ bias, const float* __restrict__ res,
        bf16* __restrict__ Cb, float* __restrict__ Cf,
        int M, int N, int K, int relu) {
    extern __shared__ char smg[];
    int row0 = blockIdx.y * 128, col0 = blockIdx.x * 128;
    int tid = threadIdx.x;
    int wid = tid >> 5, lane = tid & 31;
    int g = lane >> 2, t = lane & 3;
    int wm = wid & 1, wn = wid >> 1;
    int tl = lane >> 3, rr = lane & 7;

    float c[4][4][4];
#pragma unroll
    for (int i = 0; i < 4; i++)
#pragma unroll
        for (int j = 0; j < 4; j++)
#pragma unroll
            for (int r = 0; r < 4; r++) c[i][j][r] = 0.f;

    int nIter = K >> 5;
    auto loadStage = [&](int st, int k0g) {
        bf16 (*As)[40]  = (bf16(*)[40])(smg + st * ASZ);
        bf16 (*Bs)[136] = (bf16(*)[136])(smg + 3 * ASZ + st * BSZ);
#pragma unroll
        for (int i = 0; i < 2; i++) {
            int idx = tid + i * 256;
            int m = idx >> 2, kq = (idx & 3) * 8;
            cpa16(&As[m][kq], A + (size_t)(row0 + m) * K + k0g + kq);
        }
#pragma unroll
        for (int i = 0; i < 2; i++) {
            int idx = tid + i * 256;
            int k = idx >> 4, nq = (idx & 15) * 8;
            cpa16(&Bs[k][nq], W + (size_t)(k0g + k) * N + col0 + nq);
        }
    };
#pragma unroll
    for (int p = 0; p < 2; p++) {
        if (p < nIter) loadStage(p, p << 5);
        cp_commit();
    }
    for (int it = 0; it < nIter; ++it) {
        int st = it % 3;
        bf16 (*As)[40]  = (bf16(*)[40])(smg + st * ASZ);
        bf16 (*Bs)[136] = (bf16(*)[136])(smg + 3 * ASZ + st * BSZ);
        if (it + 1 < nIter) cp_wait1(); else cp_wait0();
        __syncthreads();
        int nx = it + 2;
        if (nx < nIter) loadStage(nx % 3, nx << 5);
        cp_commit();
#pragma unroll
        for (int ks = 0; ks < 2; ks++) {
            int k0 = ks * 16;
            unsigned af[4][4];
#pragma unroll
            for (int mt = 0; mt < 4; mt++)
                ldm_x4(af[mt], &As[wm * 64 + mt * 16 + (lane & 15)][k0 + (lane >> 4) * 8]);
            unsigned bf[4][2];
#pragma unroll
            for (int nb = 0; nb < 2; nb++) {
                unsigned r4[4];
                ldm_x4_t(r4, &Bs[k0 + (tl & 1) * 8 + rr][wn * 32 + nb * 16 + (tl >> 1) * 8]);
                bf[nb * 2 + 0][0] = r4[0]; bf[nb * 2 + 0][1] = r4[1];
                bf[nb * 2 + 1][0] = r4[2]; bf[nb * 2 + 1][1] = r4[3];
            }
#pragma unroll
            for (int mt = 0; mt < 4; mt++)
#pragma unroll
                for (int nt = 0; nt < 4; nt++) mmabf(c[mt][nt], af[mt], bf[nt]);
        }
    }
#pragma unroll
    for (int mt = 0; mt < 4; mt++) {
        int r = row0 + wm * 64 + mt * 16 + g;
#pragma unroll
        for (int nt = 0; nt < 4; nt++) {
            int cc = col0 + wn * 32 + nt * 8 + 2 * t;
            float b0 = bias[cc], b1 = bias[cc + 1];
            float v0 = c[mt][nt][0] + b0, v1 = c[mt][nt][1] + b1;
            float v2 = c[mt][nt][2] + b0, v3 = c[mt][nt][3] + b1;
            if (res) {
                v0 += res[(size_t)r * N + cc];       v1 += res[(size_t)r * N + cc + 1];
                v2 += res[(size_t)(r + 8) * N + cc]; v3 += res[(size_t)(r + 8) * N + cc + 1];
            }
            if (relu) {
                v0 = fmaxf(v0, 0.f); v1 = fmaxf(v1, 0.f);
                v2 = fmaxf(v2, 0.f); v3 = fmaxf(v3, 0.f);
            }
            if (Cf) {
                *(float2*)(Cf + (size_t)r * N + cc)       = make_float2(v0, v1);
                *(float2*)(Cf + (size_t)(r + 8) * N + cc) = make_float2(v2, v3);
            }
            if (Cb) {
                *(bf162*)(Cb + (size_t)r * N + cc)       = __float22bfloat162_rn(make_float2(v0, v1));
                *(bf162*)(Cb + (size_t)(r + 8) * N + cc) = __float22bfloat162_rn(make_float2(v2, v3));
            }
        }
    }
}

// =====================================================================
// Fused flash attention, double-buffered K/V chunks (LPT for causal)
// =====================================================================
#define KVB 36864
#define FLASH_SMEM (18432 + 2*KVB + 1024)

template <int CAUSAL>
__global__ void __launch_bounds__(256, 1) flash_kernel(
        const bf16* __restrict__ Qp, int qStride,
        const bf16* __restrict__ Kp, const bf16* __restrict__ Vp, int kvStride,
        const int* __restrict__ mask, int maskStride,
        bf16* __restrict__ Op, int Lq, int Lk) {
    extern __shared__ char sm[];
    bf16 (*Qs)[72] = (bf16(*)[72])(sm);
    int* mS = (int*)(sm + 18432 + 2 * KVB);

    int bx = CAUSAL ? (gridDim.x - 1 - blockIdx.x) : blockIdx.x;
    int m0 = bx * 128;
    int z = blockIdx.y, b = z / NHEAD, h = z % NHEAD;
    const bf16* Qb = Qp + (size_t)b * Lq * qStride + h * DK;
    const bf16* Kb = Kp + (size_t)b * Lk * kvStride + h * DK;
    const bf16* Vb = Vp + (size_t)b * Lk * kvStride + h * DK;
    bf16* Ob = Op + (size_t)b * Lq * D_MODEL + h * DK;
    const int* mrow = mask + (size_t)b * maskStride;

    int tid = threadIdx.x, w = tid >> 5, lane = tid & 31;
    int g = lane >> 2, t = lane & 3;
    int tl = lane >> 3, rr = lane & 7;
    const float scale = 0.125f;

    auto loadKV = [&](int buf, int n0) {
        bf16 (*Ks)[72] = (bf16(*)[72])(sm + 18432 + buf * KVB);
        bf16 (*Vs)[72] = (bf16(*)[72])(sm + 18432 + buf * KVB + KVB / 2);
#pragma unroll
        for (int i = 0; i < 4; i++) {
            int idx = tid + i * 256;
            int r = idx >> 3, cq = (idx & 7) * 8;
            cpa16(&Ks[r][cq], Kb + (size_t)(n0 + r) * kvStride + cq);
            cpa16(&Vs[r][cq], Vb + (size_t)(n0 + r) * kvStride + cq);
        }
        if (tid < 128) mS[buf * 128 + tid] = mrow[n0 + tid];
    };

    int nChunks = CAUSAL ? (m0 / 128 + 1) : (Lk / 128);

#pragma unroll
    for (int i = 0; i < 4; i++) {
        int idx = tid + i * 256;
        int r = idx >> 3, cq = (idx & 7) * 8;
        cpa16(&Qs[r][cq], Qb + (size_t)(m0 + r) * qStride + cq);
    }
    cp_commit();
    loadKV(0, 0);
    cp_commit();
    cp_wait1();
    __syncthreads();

    unsigned qf[4][4];
#pragma unroll
    for (int ks = 0; ks < 4; ks++)
        ldm_x4(qf[ks], &Qs[w * 16 + (lane & 15)][ks * 16 + (lane >> 4) * 8]);

    float o[8][4];
#pragma unroll
    for (int i = 0; i < 8; i++)
#pragma unroll
        for (int j = 0; j < 4; j++) o[i][j] = 0.f;
    float mrun[2] = {-1e30f, -1e30f}, lrun[2] = {0.f, 0.f};
    int rowg = m0 + w * 16 + g;

    for (int ch = 0; ch < nChunks; ch++) {
        int n0 = ch * 128;
        int bu = ch & 1;
        bf16 (*Ks)[72] = (bf16(*)[72])(sm + 18432 + bu * KVB);
        bf16 (*Vs)[72] = (bf16(*)[72])(sm + 18432 + bu * KVB + KVB / 2);
        const int* mSb = mS + bu * 128;
        if (ch + 1 < nChunks) { loadKV(bu ^ 1, n0 + 128); cp_commit(); cp_wait1(); }
        else                  { cp_commit(); cp_wait0(); }
        __syncthreads();

        float s[16][4];
#pragma unroll
        for (int nt = 0; nt < 16; nt++)
#pragma unroll
            for (int j = 0; j < 4; j++) s[nt][j] = 0.f;
#pragma unroll
        for (int ks = 0; ks < 4; ks++) {
            int k0 = ks * 16;
#pragma unroll
            for (int nt = 0; nt < 16; nt++) {
                unsigned bfr[2];
                int nc = nt * 8 + g;
                bfr[0] = *(const unsigned*)&Ks[nc][k0 + 2 * t];
                bfr[1] = *(const unsigned*)&Ks[nc][k0 + 8 + 2 * t];
                mmabf(s[nt], qf[ks], bfr);
            }
        }
#pragma unroll
        for (int nt = 0; nt < 16; nt++) {
            int cl = nt * 8 + 2 * t;
            int c0 = n0 + cl, c1 = c0 + 1;
            bool k0ok = mSb[cl] != 0, k1ok = mSb[cl + 1] != 0;
            bool v0 = k0ok && (!CAUSAL || c0 <= rowg);
            bool v1 = k1ok && (!CAUSAL || c1 <= rowg);
            bool v2 = k0ok && (!CAUSAL || c0 <= rowg + 8);
            bool v3 = k1ok && (!CAUSAL || c1 <= rowg + 8);
            s[nt][0] = v0 ? s[nt][0] * scale : -10000.0f;
            s[nt][1] = v1 ? s[nt][1] * scale : -10000.0f;
            s[nt][2] = v2 ? s[nt][2] * scale : -10000.0f;
            s[nt][3] = v3 ? s[nt][3] * scale : -10000.0f;
        }
        float mg0 = -1e30f, mg1 = -1e30f;
#pragma unroll
        for (int nt = 0; nt < 16; nt++) {
            mg0 = fmaxf(mg0, fmaxf(s[nt][0], s[nt][1]));
            mg1 = fmaxf(mg1, fmaxf(s[nt][2], s[nt][3]));
        }
#pragma unroll
        for (int off = 1; off < 4; off <<= 1) {
            mg0 = fmaxf(mg0, __shfl_xor_sync(0xffffffffu, mg0, off));
            mg1 = fmaxf(mg1, __shfl_xor_sync(0xffffffffu, mg1, off));
        }
        float mn0 = fmaxf(mrun[0], mg0), mn1 = fmaxf(mrun[1], mg1);
        float a0 = __expf(mrun[0] - mn0), a1 = __expf(mrun[1] - mn1);
        float sum0 = 0.f, sum1 = 0.f;
#pragma unroll
        for (int nt = 0; nt < 16; nt++) {
            s[nt][0] = __expf(s[nt][0] - mn0);
            s[nt][1] = __expf(s[nt][1] - mn0);
            s[nt][2] = __expf(s[nt][2] - mn1);
            s[nt][3] = __expf(s[nt][3] - mn1);
            sum0 += s[nt][0] + s[nt][1];
            sum1 += s[nt][2] + s[nt][3];
        }
#pragma unroll
        for (int off = 1; off < 4; off <<= 1) {
            sum0 += __shfl_xor_sync(0xffffffffu, sum0, off);
            sum1 += __shfl_xor_sync(0xffffffffu, sum1, off);
        }
        lrun[0] = lrun[0] * a0 + sum0;
        lrun[1] = lrun[1] * a1 + sum1;
        mrun[0] = mn0; mrun[1] = mn1;
#pragma unroll
        for (int ot = 0; ot < 8; ot++) {
            o[ot][0] *= a0; o[ot][1] *= a0;
            o[ot][2] *= a1; o[ot][3] *= a1;
        }
#pragma unroll
        for (int j = 0; j < 8; j++) {
            unsigned pa[4];
            pa[0] = packbf(s[2 * j][0],     s[2 * j][1]);
            pa[1] = packbf(s[2 * j][2],     s[2 * j][3]);
            pa[2] = packbf(s[2 * j + 1][0], s[2 * j + 1][1]);
            pa[3] = packbf(s[2 * j + 1][2], s[2 * j + 1][3]);
#pragma unroll
            for (int nb = 0; nb < 4; nb++) {
                unsigned r4[4];
                ldm_x4_t(r4, &Vs[j * 16 + (tl & 1) * 8 + rr][nb * 16 + (tl >> 1) * 8]);
                mmabf(o[nb * 2 + 0], pa, r4);
                mmabf(o[nb * 2 + 1], pa, r4 + 2);
            }
        }
        __syncthreads();
    }
    float inv0 = 1.0f / lrun[0], inv1 = 1.0f / lrun[1];
#pragma unroll
    for (int ot = 0; ot < 8; ot++) {
        int col = ot * 8 + 2 * t;
        *(bf162*)(Ob + (size_t)rowg * D_MODEL + col) =
            __float22bfloat162_rn(make_float2(o[ot][0] * inv0, o[ot][1] * inv0));
        *(bf162*)(Ob + (size_t)(rowg + 8) * D_MODEL + col) =
            __float22bfloat162_rn(make_float2(o[ot][2] * inv1, o[ot][3] * inv1));
    }
}

// ---------------- final log_softmax (warp per row, 512 cols) ----------------
__global__ void logsoftmax_kernel(const float* __restrict__ X, float* __restrict__ Out) {
    int warp = (blockIdx.x * blockDim.x + threadIdx.x) >> 5;
    int lane = threadIdx.x & 31;
    if (warp >= MT) return;
    const float* r = X + (size_t)warp * VOCAB;
    float v[16], mx = -1e30f;
#pragma unroll
    for (int j = 0; j < 16; j++) { v[j] = r[lane + j * 32]; mx = fmaxf(mx, v[j]); }
#pragma unroll
    for (int o = 16; o > 0; o >>= 1) mx = fmaxf(mx, __shfl_xor_sync(0xffffffffu, mx, o));
    float sum = 0.f;
#pragma unroll
    for (int j = 0; j < 16; j++) sum += expf(v[j] - mx);
#pragma unroll
    for (int o = 16; o > 0; o >>= 1) sum += __shfl_xor_sync(0xffffffffu, sum, o);
    float lse = mx + logf(sum);
    float* out = Out + (size_t)warp * VOCAB;
#pragma unroll
    for (int j = 0; j < 16; j++) out[lane + j * 32] = v[j] - lse;
}

// ---------------- host driver ----------------
template <typename T>
static T* symp(const void* s) {
    void* p = nullptr;
    cudaGetSymbolAddress(&p, s);
    return (T*)p;
}

extern "C" void kernel_launch(void* const* d_in, const int* in_sizes, int n_in,
                              void* d_out, int out_size) {
    const int*   ids    = (const int*)d_in[0];
    const int*   attm   = (const int*)d_in[1];
    const float* src    = (const float*)d_in[2];
    const int*   srcm   = (const int*)d_in[3];
    const float* emb    = (const float*)d_in[4];
    const float* sa_W   = (const float*)d_in[5];
    const float* sa_b   = (const float*)d_in[6];
    const float* ca_W   = (const float*)d_in[7];
    const float* ca_b   = (const float*)d_in[8];
    const float* ln_a   = (const float*)d_in[9];
    const float* ln_b   = (const float*)d_in[10];
    const float* ffn_w1 = (const float*)d_in[11];
    const float* ffn_b1 = (const float*)d_in[12];
    const float* ffn_w2 = (const float*)d_in[13];
    const float* ffn_b2 = (const float*)d_in[14];
    const float* fin_a  = (const float*)d_in[15];
    const float* fin_b  = (const float*)d_in[16];
    const float* lm_W   = (const float*)d_in[17];
    const float* lm_b   = (const float*)d_in[18];
    float* out = (float*)d_out;

    float* x    = symp<float>(g_x);
    float* lg   = symp<float>(g_lg);
    bf16* hb    = symp<bf16>(g_hb);
    bf16* qb    = symp<bf16>(g_qb);
    bf16* qkv   = symp<bf16>(g_qkv);
    bf16* kvL   = symp<bf16>(g_kvL);
    bf16* ab    = symp<bf16>(g_ab);
    bf16* fb    = symp<bf16>(g_fb);
    bf16* wsa   = symp<bf16>(g_wsa);
    bf16* wca   = symp<bf16>(g_wca);
    bf16* wqkv  = symp<bf16>(g_wqkv);
    bf16* wkv   = symp<bf16>(g_wkv);
    float* bqkv = symp<float>(g_bqkv);
    float* bkv  = symp<float>(g_bkv);
    bf16* w1    = symp<bf16>(g_w1);
    bf16* w2    = symp<bf16>(g_w2);
    bf16* wlm   = symp<bf16>(g_wlm);
    bf16* srcb  = symp<bf16>(g_srcb);

    static bool inited = false;
    static cudaStream_t s2;
    static cudaEvent_t evFork, evKv[NLAYER];
    if (!inited) {
        cudaFuncSetAttribute(flash_kernel<1>, cudaFuncAttributeMaxDynamicSharedMemorySize, FLASH_SMEM);
        cudaFuncSetAttribute(flash_kernel<0>, cudaFuncAttributeMaxDynamicSharedMemorySize, FLASH_SMEM);
        cudaFuncSetAttribute(gemm_bf, cudaFuncAttributeMaxDynamicSharedMemorySize, GEMM_SMEM);
        cudaStreamCreateWithFlags(&s2, cudaStreamNonBlocking);
        cudaEventCreateWithFlags(&evFork, cudaEventDisableTiming);
        for (int i = 0; i < NLAYER; i++)
            cudaEventCreateWithFlags(&evKv[i], cudaEventDisableTiming);
        inited = true;
    }

    // ---- one-time-per-launch conversions / repacks ----
    {
        int nF4 = NLAYER * D_MODEL * D_FF / 4;
        conv3_kernel<<<2048, 256>>>((const float4*)sa_W, (const float4*)ca_W,
                                    (uint2*)wsa, (uint2*)wca);
        f2bf4_kernel<<<(nF4 + 1023) / 1024, 256>>>((const float4*)ffn_w1, (uint2*)w1, nF4);
        f2bf4_kernel<<<(nF4 + 1023) / 1024, 256>>>((const float4*)ffn_w2, (uint2*)w2, nF4);
        f2bf4_kernel<<<(D_MODEL * VOCAB / 4 + 1023) / 1024, 256>>>((const float4*)lm_W, (uint2*)wlm, D_MODEL * VOCAB / 4);
        f2bf4_kernel<<<(MS * D_MODEL / 4 + 1023) / 1024, 256>>>((const float4*)src, (uint2*)srcb, MS * D_MODEL / 4);
        int tq4 = NLAYER * D_MODEL * 3 * D_MODEL / 4;
        int tk4 = NLAYER * D_MODEL * 2 * D_MODEL / 4;
        pack_w4<<<(tq4 + 1023) / 1024, 256>>>(sa_W, (uint2*)wqkv, 3, 0, tq4);
        pack_w4<<<(tk4 + 1023) / 1024, 256>>>(ca_W, (uint2*)wkv, 2, 1, tk4);
        pack_b2<<<(NLAYER * 5 * D_MODEL + 255) / 256, 256>>>(sa_b, ca_b, bqkv, bkv);
    }

    // ---- fork: all 4 cross-KV projections on s2 (depend only on prep) ----
    dim3 gKV(2 * D_MODEL / 128, MS / 128);    // (8, 32)
    cudaEventRecord(evFork, 0);
    cudaStreamWaitEvent(s2, evFork, 0);
    for (int i = 0; i < NLAYER; i++) {
        gemm_bf<<<gKV, 256, GEMM_SMEM, s2>>>(srcb, wkv + (size_t)i * D_MODEL * 2 * D_MODEL,
                              bkv + (size_t)i * 2 * D_MODEL, nullptr,
                              kvL + (size_t)i * MS * 2 * D_MODEL, nullptr,
                              MS, 2 * D_MODEL, D_MODEL, 0);
        cudaEventRecord(evKv[i], s2);
    }

    pe_kernel<<<(LT * D_MODEL + 255) / 256, 256>>>();
    embed_kernel<<<(MT * D_MODEL + 255) / 256, 256>>>(ids, emb);

    dim3 gProjT(D_MODEL / 128, MT / 128);     // (4, 64)
    dim3 gQKV(3 * D_MODEL / 128, MT / 128);   // (12, 64)
    dim3 gFfn1(D_FF / 128, MT / 128);         // (16, 64)
    dim3 gFlash(LT / 128, BATCH * NHEAD);
    const int lnGrid = MT / 8;

    for (int i = 0; i < NLAYER; i++) {
        const bf16*  saW = wsa + (size_t)i * 4 * D_MODEL * D_MODEL;
        const float* sab = sa_b + (size_t)i * 4 * D_MODEL;
        const bf16*  caW = wca + (size_t)i * 4 * D_MODEL * D_MODEL;
        const float* cab = ca_b + (size_t)i * 4 * D_MODEL;
        const float* lnA = ln_a + (size_t)i * 3 * D_MODEL;
        const float* lnB = ln_b + (size_t)i * 3 * D_MODEL;
        bf16* kvi = kvL + (size_t)i * MS * 2 * D_MODEL;

        // ---- self-attention ----
        ln_kernel<<<lnGrid, 256>>>(x, hb, lnA + 0 * D_MODEL, lnB + 0 * D_MODEL);
        gemm_bf<<<gQKV, 256, GEMM_SMEM>>>(hb, wqkv + (size_t)i * D_MODEL * 3 * D_MODEL,
                               bqkv + (size_t)i * 3 * D_MODEL, nullptr, qkv, nullptr,
                               MT, 3 * D_MODEL, D_MODEL, 0);
        flash_kernel<1><<<gFlash, 256, FLASH_SMEM>>>(
            qkv, 3 * D_MODEL, qkv + D_MODEL, qkv + 2 * D_MODEL, 3 * D_MODEL,
            attm, LFULL, ab, LT, LT);
        gemm_bf<<<gProjT, 256, GEMM_SMEM>>>(ab, saW + 3 * D_MODEL * D_MODEL, sab + 3 * D_MODEL,
                                 x, nullptr, x, MT, D_MODEL, D_MODEL, 0);

        // ---- cross-attention ----
        ln_kernel<<<lnGrid, 256>>>(x, hb, lnA + 1 * D_MODEL, lnB + 1 * D_MODEL);
        gemm_bf<<<gProjT, 256, GEMM_SMEM>>>(hb, caW + 0 * D_MODEL * D_MODEL, cab + 0 * D_MODEL,
                                 nullptr, qb, nullptr, MT, D_MODEL, D_MODEL, 0);
        cudaStreamWaitEvent(0, evKv[i], 0);
        flash_kernel<0><<<gFlash, 256, FLASH_SMEM>>>(
            qb, D_MODEL, kvi, kvi + D_MODEL, 2 * D_MODEL,
            srcm, SRC_S, ab, LT, SRC_S);
        gemm_bf<<<gProjT, 256, GEMM_SMEM>>>(ab, caW + 3 * D_MODEL * D_MODEL, cab + 3 * D_MODEL,
                                 x, nullptr, x, MT, D_MODEL, D_MODEL, 0);

        // ---- FFN ----
        ln_kernel<<<lnGrid, 256>>>(x, hb, lnA + 2 * D_MODEL, lnB + 2 * D_MODEL);
        gemm_bf<<<gFfn1, 256, GEMM_SMEM>>>(hb, w1 + (size_t)i * D_MODEL * D_FF,
                                ffn_b1 + (size_t)i * D_FF, nullptr, fb, nullptr,
                                MT, D_FF, D_MODEL, 1);
        gemm_bf<<<gProjT, 256, GEMM_SMEM>>>(fb, w2 + (size_t)i * D_FF * D_MODEL,
                                ffn_b2 + (size_t)i * D_MODEL, x, nullptr, x,
                                MT, D_MODEL, D_FF, 0);
    }

    ln_kernel<<<lnGrid, 256>>>(x, hb, fin_a, fin_b);
    gemm_bf<<<dim3(VOCAB / 128, MT / 128), 256, GEMM_SMEM>>>(hb, wlm, lm_b, nullptr, nullptr, lg,
                                                  MT, VOCAB, D_MODEL, 0);
    logsoftmax_kernel<<<(MT * 32 + 255) / 256, 256>>>(lg, out);
}